// round 8
// baseline (speedup 1.0000x reference)
#include <cuda_runtime.h>
#include <cuda_bf16.h>
#include <math.h>

// Problem constants
#define B  2
#define N  512
#define FI 256
#define FO 128
#define ALPHA 0.2f

#define TI 32
#define TJ 32
#define NTILE (B * (N/TI) * (N/TJ))   // 512 e-tiles
#define NCTA  128
#define NTHR  256

typedef unsigned long long ull;

// Scratch (no allocations allowed -> device globals)
__device__ float g_Wh[B * N * FO];     // 512 KB
__device__ float g_e [B * N * N];      // 2 MB (masked e: -inf where adj==0)
__device__ float g_c [B * N];          // ci = sum_o a_o * Wh[i,o]
__device__ float g_part[NTILE];

// grid-barrier state (zero-init; reset by last CTA each launch -> replay-safe)
__device__ unsigned g_bar_cnt[2];
__device__ unsigned g_bar_flag[2];
__device__ unsigned g_done;

__device__ __forceinline__ ull fadd2(ull a, ull b) {
    ull d; asm("add.rn.f32x2 %0, %1, %2;" : "=l"(d) : "l"(a), "l"(b)); return d;
}
__device__ __forceinline__ ull ffma2(ull a, ull b, ull c) {
    ull d; asm("fma.rn.f32x2 %0, %1, %2, %3;" : "=l"(d) : "l"(a), "l"(b), "l"(c)); return d;
}
__device__ __forceinline__ float lo_f(ull v) { return __uint_as_float((unsigned)(v & 0xFFFFFFFFull)); }
__device__ __forceinline__ float hi_f(ull v) { return __uint_as_float((unsigned)(v >> 32)); }

#define ABS2_MASK 0x7FFFFFFF7FFFFFFFull

__device__ __forceinline__ void grid_barrier(int slot) {
    __syncthreads();
    if (threadIdx.x == 0) {
        __threadfence();
        unsigned t = atomicAdd(&g_bar_cnt[slot], 1);
        if (t == NCTA - 1) {
            atomicExch(&g_bar_flag[slot], 1u);
        } else {
            while (*((volatile unsigned*)&g_bar_flag[slot]) == 0u) {}
        }
        __threadfence();
    }
    __syncthreads();
}

// ---- overlapping shared-memory layouts ----
struct SmemP1 {
    float  xs[8][FI];        // 8 KB
    float4 wt[32][FO/4];     // 16 KB
};
struct SmemP2 {
    float4 tIs[TI * 33];     // 16.9 KB
    float4 tJs[TJ * 33];     // 16.9 KB
    float4 aS[FO / 4];
    float  cIs[TI];
    float  cJs[TJ];
    float  wsum[8];
};
struct SmemP34 {
    float  att[8][N];        // 16 KB
    float4 wht[32][FO/4];    // 16 KB
    float  red[NTHR];        // 1 KB
    float  rnorm[8];
};

__global__ void __launch_bounds__(NTHR, 1)
k_all(const float* __restrict__ x, const int* __restrict__ adj,
      const float* __restrict__ W, const float* __restrict__ a_fc,
      float* __restrict__ out) {
    __shared__ __align__(16) char smem_raw[36000];
    const int cta = blockIdx.x;
    const int tx  = threadIdx.x;

    // ======================= P1: Wh = x @ W  (+ ci) =======================
    {
        SmemP1& s = *reinterpret_cast<SmemP1*>(smem_raw);
        const int row0 = cta * 8;
        {
            const float4* x4 = reinterpret_cast<const float4*>(x + row0 * FI);
            float4* xs4 = reinterpret_cast<float4*>(&s.xs[0][0]);
            xs4[tx]        = x4[tx];
            xs4[tx + NTHR] = x4[tx + NTHR];
        }
        const int r    = tx >> 5;      // row within CTA (warp per row)
        const int lane = tx & 31;      // float4 column
        const float4* W4 = reinterpret_cast<const float4*>(W);
        float4 acc = make_float4(0.f, 0.f, 0.f, 0.f);

        for (int kt = 0; kt < FI; kt += 32) {
            __syncthreads();
            #pragma unroll
            for (int p = 0; p < 4; p++) {
                const int idx = tx + NTHR * p;       // 0..1023
                const int k  = idx >> 5;
                const int o4 = idx & 31;
                s.wt[k][o4] = W4[(kt + k) * (FO/4) + o4];
            }
            __syncthreads();
            #pragma unroll
            for (int k = 0; k < 32; k++) {
                const float  xv = s.xs[r][kt + k];   // warp broadcast
                const float4 w  = s.wt[k][lane];     // conflict-free LDS.128
                acc.x = fmaf(xv, w.x, acc.x);
                acc.y = fmaf(xv, w.y, acc.y);
                acc.z = fmaf(xv, w.z, acc.z);
                acc.w = fmaf(xv, w.w, acc.w);
            }
        }
        reinterpret_cast<float4*>(g_Wh)[(row0 + r) * (FO/4) + lane] = acc;

        const float4 av = reinterpret_cast<const float4*>(a_fc)[lane];
        float m = acc.x * av.x + acc.y * av.y + acc.z * av.z + acc.w * av.w;
        #pragma unroll
        for (int off = 16; off > 0; off >>= 1)
            m += __shfl_xor_sync(0xFFFFFFFFu, m, off);
        if (lane == 0) g_c[row0 + r] = m;
    }
    grid_barrier(0);

    // ======================= P2: masked e + norm partials =======================
    {
        SmemP2& s = *reinterpret_cast<SmemP2*>(smem_raw);
        const int lx = tx & 31;
        const int ty = tx >> 5;
        const float4* Wh4 = reinterpret_cast<const float4*>(g_Wh);

        if (tx < FO / 4)
            s.aS[tx] = reinterpret_cast<const float4*>(a_fc)[tx];

        for (int t = 0; t < 4; t++) {
            const int tile = cta * 4 + t;
            const int b  = tile >> 8;
            const int it = ((tile >> 4) & 15) * TI;
            const int jt = (tile & 15) * TJ;

            __syncthreads();   // smem reuse from previous tile / phase
            if (tx >= 64 && tx < 96)   s.cIs[tx - 64] = 0.6f * g_c[b * N + it + (tx - 64)];
            if (tx >= 96 && tx < 128)  s.cJs[tx - 96] = 0.6f * g_c[b * N + jt + (tx - 96)];
            #pragma unroll
            for (int p = 0; p < 4; p++) {
                const int idx = tx + NTHR * p;
                const int r = idx >> 5, c = idx & 31;
                s.tIs[r * 33 + c] = Wh4[(b * N + it + r) * (FO / 4) + c];
                s.tJs[r * 33 + c] = Wh4[(b * N + jt + r) * (FO / 4) + c];
            }
            __syncthreads();

            const ulonglong2* tI2 = reinterpret_cast<const ulonglong2*>(s.tIs);
            const ulonglong2* tJ2 = reinterpret_cast<const ulonglong2*>(s.tJs);
            const ulonglong2* a2  = reinterpret_cast<const ulonglong2*>(s.aS);

            ull accA[4] = {0, 0, 0, 0};
            ull accB[4] = {0, 0, 0, 0};

            #pragma unroll 4
            for (int oc = 0; oc < FO / 4; oc++) {
                const ulonglong2 wj = tJ2[lx * 33 + oc];   // lane-varying
                const ulonglong2 av = a2[oc];              // broadcast
                #pragma unroll
                for (int k = 0; k < 4; k++) {
                    const ulonglong2 wi = tI2[(ty + 8 * k) * 33 + oc];  // warp bcast
                    ull s0 = fadd2(wi.x, wj.x) & ABS2_MASK;
                    ull s1 = fadd2(wi.y, wj.y) & ABS2_MASK;
                    accA[k] = ffma2(s0, av.x, accA[k]);
                    accB[k] = ffma2(s1, av.y, accB[k]);
                }
            }

            float ss = 0.f;
            const float cj = s.cJs[lx];
            #pragma unroll
            for (int k = 0; k < 4; k++) {
                const ull tt = fadd2(accA[k], accB[k]);
                const float absSum = lo_f(tt) + hi_f(tt);
                const float e = fmaf(0.4f, absSum, s.cIs[ty + 8 * k] + cj);
                const int i = it + ty + 8 * k;
                const int adjv = adj[(b * N + i) * N + jt + lx];
                g_e[(b * N + i) * N + jt + lx] = adjv ? e : -INFINITY;
                ss = fmaf(e, e, ss);   // norm uses UNMASKED e (reference order)
            }

            #pragma unroll
            for (int off = 16; off > 0; off >>= 1)
                ss += __shfl_xor_sync(0xFFFFFFFFu, ss, off);
            if (lx == 0) s.wsum[ty] = ss;
            __syncthreads();
            if (tx == 0) {
                float acc = 0.f;
                #pragma unroll
                for (int w = 0; w < 8; w++) acc += s.wsum[w];
                g_part[tile] = acc;
            }
        }
    }
    grid_barrier(1);

    // ============== P2.5 norm + P3 softmax + P4 att@Wh + ELU ==============
    {
        SmemP34& s = *reinterpret_cast<SmemP34*>(smem_raw);
        const int b  = cta >> 6;
        const int i0 = (cta & 63) * 8;

        // --- P2.5: redundant deterministic norm reduction (identical order) ---
        s.red[tx] = g_part[tx] + g_part[tx + 256];
        __syncthreads();
        #pragma unroll
        for (int st = 128; st > 0; st >>= 1) {
            if (tx < st) s.red[tx] += s.red[tx + st];
            __syncthreads();
        }
        const float inv = 1.0f / sqrtf(s.red[0]);
        __syncthreads();

        // --- P3: softmax weights (unnormalized exp) for this CTA's 8 rows ---
        {
            const int w = tx >> 5, lane = tx & 31;
            const float4* e4 = reinterpret_cast<const float4*>(g_e + (b * N + i0 + w) * N);
            float4* att4 = reinterpret_cast<float4*>(&s.att[w][0]);

            float4 ev[4];
            float mx = -INFINITY;
            #pragma unroll
            for (int m = 0; m < 4; m++) {
                const int c = lane + 32 * m;
                float4 v = e4[c];
                v.x *= inv; v.y *= inv; v.z *= inv; v.w *= inv;  // -inf stays -inf
                ev[m] = v;
                mx = fmaxf(mx, fmaxf(fmaxf(v.x, v.y), fmaxf(v.z, v.w)));
            }
            #pragma unroll
            for (int off = 16; off > 0; off >>= 1)
                mx = fmaxf(mx, __shfl_xor_sync(0xFFFFFFFFu, mx, off));

            float sum = 0.f;
            #pragma unroll
            for (int m = 0; m < 4; m++) {
                float4 v = ev[m];
                v.x = __expf(v.x - mx);
                v.y = __expf(v.y - mx);
                v.z = __expf(v.z - mx);
                v.w = __expf(v.w - mx);
                att4[lane + 32 * m] = v;
                sum += (v.x + v.y) + (v.z + v.w);
            }
            #pragma unroll
            for (int off = 16; off > 0; off >>= 1)
                sum += __shfl_xor_sync(0xFFFFFFFFu, sum, off);
            if (lane == 0) s.rnorm[w] = 1.0f / sum;
        }
        __syncthreads();

        // --- P4: h'[row, o] = sum_j att[row][j] * Wh[b, j, o] ---
        const int iy = tx >> 5;        // warp = row
        const int o4 = tx & 31;        // float4 column
        float4 acc = make_float4(0.f, 0.f, 0.f, 0.f);

        for (int kt = 0; kt < N; kt += 32) {
            __syncthreads();
            #pragma unroll
            for (int p = 0; p < 4; p++) {
                const int idx = tx + NTHR * p;
                const int kk = idx >> 5, oc = idx & 31;
                s.wht[kk][oc] = reinterpret_cast<const float4*>(
                    g_Wh + (b * N + kt + kk) * FO)[oc];
            }
            __syncthreads();
            #pragma unroll
            for (int k = 0; k < 32; k++) {
                const float  a = s.att[iy][kt + k];  // warp broadcast
                const float4 w = s.wht[k][o4];       // conflict-free LDS.128
                acc.x = fmaf(a, w.x, acc.x);
                acc.y = fmaf(a, w.y, acc.y);
                acc.z = fmaf(a, w.z, acc.z);
                acc.w = fmaf(a, w.w, acc.w);
            }
        }

        const float rn = s.rnorm[iy];
        float4 v;
        v.x = acc.x * rn; v.y = acc.y * rn; v.z = acc.z * rn; v.w = acc.w * rn;
        v.x = (v.x > 0.f) ? v.x : expm1f(v.x);
        v.y = (v.y > 0.f) ? v.y : expm1f(v.y);
        v.z = (v.z > 0.f) ? v.z : expm1f(v.z);
        v.w = (v.w > 0.f) ? v.w : expm1f(v.w);
        reinterpret_cast<float4*>(out + (b * N + i0 + iy) * FO)[o4] = v;
    }

    // ---- reset barrier state for the next graph replay ----
    __syncthreads();
    if (tx == 0) {
        __threadfence();
        if (atomicAdd(&g_done, 1) == NCTA - 1) {
            g_bar_cnt[0] = 0; g_bar_cnt[1] = 0;
            g_bar_flag[0] = 0; g_bar_flag[1] = 0;
            g_done = 0;
            __threadfence();
        }
    }
}

// ---------------------------------------------------------------------------
extern "C" void kernel_launch(void* const* d_in, const int* in_sizes, int n_in,
                              void* d_out, int out_size) {
    const float* x    = (const float*)d_in[0];   // [B,N,FI]
    const int*   adj  = (const int*)  d_in[1];   // [B,N,N]
    const float* W    = (const float*)d_in[2];   // [FI,FO]
    const float* a_fc = (const float*)d_in[3];   // [FO]
    float* out = (float*)d_out;                  // [B,N,FO]

    k_all<<< NCTA, NTHR >>>(x, adj, W, a_fc, out);
}